// round 15
// baseline (speedup 1.0000x reference)
#include <cuda_runtime.h>
#include <cstdint>

// ---------------- problem constants ----------------
#define Bn 16384
#define Nn 17
#define Cc 128
#define Dd 128
#define THREADS 288            // 9 warps: warps 0-7 GEMM, all 9 in prologue/agg
#define XSTR 136               // x tile row stride (mod 32 == 8: conflict-free frags)
#define USTR 264               // U12 tile row stride (mod 32 == 8)

// ---------------- device scratch ----------------
__device__ float4 g_L12[Nn*Nn];      // {l1,l1,t2,t2} per (n,m)
__device__ float  g_WB[3*16*16*64];  // W tf32 frags; 16 contiguous floats/lane/k-step

// ---------------- smem float-index offsets (R8 layout) ----------------
#define SF_XU   0                    // 153*136 = 20808 floats
#define SF_U    20808                // 128*264 = 33792 floats (U1 | U2)
#define SF_L    54600                // 289 float4 = 1156 floats
#define SF_BIAS 55756                // 128 floats
#define SMEM_FLOATS 55884
#define SMEM_BYTES  (SMEM_FLOATS*4)  // 223536

// ---------------- helpers ----------------
__device__ __forceinline__ uint32_t cvt_tf32(float f) {
    uint32_t u; asm("cvt.rn.tf32.f32 %0, %1;" : "=r"(u) : "f"(f)); return u;
}
__device__ __forceinline__ float tf32f(float f) { return __uint_as_float(cvt_tf32(f)); }
__device__ __forceinline__ void fma2(uint64_t& acc, uint64_t a, uint64_t b) {
    asm("fma.rn.f32x2 %0, %1, %2, %0;" : "+l"(acc) : "l"(a), "l"(b));
}
__device__ __forceinline__ void unpack2(uint64_t u, float& a, float& b) {
    asm("mov.b64 {%0, %1}, %2;" : "=f"(a), "=f"(b) : "l"(u));
}
__device__ __forceinline__ uint64_t pack2f(float a, float b) {
    uint64_t u; asm("mov.b64 %0, {%1, %2};" : "=l"(u) : "f"(a), "f"(b)); return u;
}
__device__ __forceinline__ void mma_tf32(float* d, uint32_t a0, uint32_t a1,
                                         uint32_t a2, uint32_t a3,
                                         uint32_t b0, uint32_t b1) {
    asm volatile("mma.sync.aligned.m16n8k8.row.col.f32.tf32.tf32.f32 "
        "{%0,%1,%2,%3}, {%4,%5,%6,%7}, {%8,%9}, {%0,%1,%2,%3};"
        : "+f"(d[0]), "+f"(d[1]), "+f"(d[2]), "+f"(d[3])
        : "r"(a0), "r"(a1), "r"(a2), "r"(a3), "r"(b0), "r"(b1));
}

// ---------------------------------------------------------------------------
// Merged setup. W fragment layout (LDG.128-friendly, proven in R13/R14):
//   g_WB[((k*16+s)*2+nw)*512 + lane*16 + ni*2 + j]
//     = tf32( W_k[c = 8s + (lane&3) + 4j][d = (lane>>2) + 8*ni + 64*nw] )
// Block 96 computes the Chebyshev basis into g_L12.
// ---------------------------------------------------------------------------
__global__ void setup_kernel(const float* __restrict__ adj, const float* __restrict__ w) {
    __shared__ float dinv[Nn];
    __shared__ float Ls[Nn*Nn];
    if (blockIdx.x < 96) {
        int idx = blockIdx.x * 512 + threadIdx.x;     // < 49152
        int j    = idx & 1;
        int ni   = (idx >> 1) & 7;
        int lane = (idx >> 4) & 31;
        int nw   = (idx >> 9) & 1;
        int s    = (idx >> 10) & 15;
        int k    = idx >> 14;
        int c = 8*s + (lane & 3) + 4*j;
        int d = (lane >> 2) + 8*ni + 64*nw;
        g_WB[idx] = tf32f(w[k*16384 + c*128 + d]);
    } else {
        int t = threadIdx.x;
        if (t < Nn) {
            float s = 0.f;
            #pragma unroll
            for (int m = 0; m < Nn; ++m) s += adj[t*Nn + m];
            dinv[t] = rsqrtf(s);
        }
        __syncthreads();
        if (t < Nn*Nn) {
            int n = t / Nn, m = t % Nn;
            Ls[t] = (n == m ? 1.f : 0.f) - dinv[n] * adj[t] * dinv[m];
        }
        __syncthreads();
        if (t < Nn*Nn) {
            int n = t / Nn, m = t % Nn;
            float a = 0.f;
            #pragma unroll
            for (int jx = 0; jx < Nn; ++jx) a = fmaf(Ls[n*Nn + jx], Ls[jx*Nn + m], a);
            float t2 = 2.f * a - (n == m ? 1.f : 0.f);
            g_L12[t] = make_float4(Ls[t], Ls[t], t2, t2);
        }
    }
}

// ---------------------------------------------------------------------------
// GEMM chunk: A frags 2x LDS.64 (pair-permuted, R8-proven conflict-free),
//             B frags 4x LDG.128 (L1-resident after wave 1)
// ---------------------------------------------------------------------------
template<int STR>
__device__ __forceinline__ void gemm_chunk(const float* Ab, const float* Bb,
                                           float acc[2][8][4]) {
    #pragma unroll 2
    for (int s = 0; s < 16; ++s) {
        const float* As = Ab + s*8;
        uint2 A[2][2];
        #pragma unroll
        for (int mi = 0; mi < 2; ++mi) {
            A[mi][0] = *(const uint2*)(As + mi*16*STR);           // {a0,a2} row g
            A[mi][1] = *(const uint2*)(As + mi*16*STR + 8*STR);   // {a1,a3} row g+8
        }
        uint4 B4[4];
        const float* Bs = Bb + s*1024;
        #pragma unroll
        for (int q = 0; q < 4; ++q) B4[q] = *(const uint4*)(Bs + q*4);
        #pragma unroll
        for (int mi = 0; mi < 2; ++mi)
            #pragma unroll
            for (int q = 0; q < 4; ++q) {
                mma_tf32(acc[mi][2*q],   A[mi][0].x, A[mi][1].x,
                         A[mi][0].y, A[mi][1].y, B4[q].x, B4[q].y);
                mma_tf32(acc[mi][2*q+1], A[mi][0].x, A[mi][1].x,
                         A[mi][0].y, A[mi][1].y, B4[q].z, B4[q].w);
            }
    }
}

// ---------------------------------------------------------------------------
// Main kernel (R8 skeleton): prologue ; agg(U1+U2 -> sU) ; 3 chunks ; epilogue
// ---------------------------------------------------------------------------
__global__ void __launch_bounds__(THREADS, 1)
graphcheb(const float* __restrict__ x, const float* __restrict__ bias,
          float* __restrict__ out) {
    extern __shared__ float sm[];
    float* sXU = sm + SF_XU;
    float* sU  = sm + SF_U;
    const ulonglong2* sLd = (const ulonglong2*)(sm + SF_L);
    float* sB  = sm + SF_BIAS;

    const int t    = threadIdx.x;
    const int lane = t & 31;
    const int warp = t >> 5;
    const int g    = lane >> 2;
    const int tq   = lane & 3;

    const int rg0    = blockIdx.x * 128;
    const int bstart = rg0 / Nn;
    const int phase  = rg0 - bstart * Nn;
    const int nb     = (rg0 + 127) / Nn - bstart + 1;   // 8 or 9 batches staged

    // ---- prologue: x -> sXU (tf32, pair-permuted), L, bias (R8 verbatim) ----
    {
        const float* xg = x + (size_t)bstart * 2176;
        const int nblk = nb * 17 * 16;
        for (int i = t; i < nblk; i += THREADS) {
            int row = i >> 4, blk = i & 15;
            const float* p = xg + row*128 + blk*8;
            float4 v0 = *(const float4*)p;
            float4 v1 = *(const float4*)(p + 4);
            uint64_t* o = (uint64_t*)(sXU + row*XSTR + blk*8);
            o[0] = pack2f(tf32f(v0.x), tf32f(v1.x));
            o[1] = pack2f(tf32f(v0.y), tf32f(v1.y));
            o[2] = pack2f(tf32f(v0.z), tf32f(v1.z));
            o[3] = pack2f(tf32f(v0.w), tf32f(v1.w));
        }
        for (int i = t; i < Nn*Nn; i += THREADS)
            ((float4*)(sm + SF_L))[i] = g_L12[i];
        if (t < Dd) sB[t] = bias[t];
    }
    __syncthreads();

    // ---- aggregation: item = (batch, col-quad, n-half). One L load / 4 cols ----
    {
        const int items = nb * 64;
        for (int it = t; it < items; it += THREADS) {
            const int bb = it >> 6;
            const int q  = (it >> 1) & 31;      // quad of permuted cols 4q..4q+3
            const int h  = it & 1;
            const int n0   = h ? 8 : 0;
            const int nend = h ? 17 : 8;
            const float* xb = sXU + bb*17*XSTR + 4*q;
            ulonglong2 xq[Nn];
            #pragma unroll
            for (int m = 0; m < Nn; ++m)
                xq[m] = *(const ulonglong2*)(xb + m*XSTR);   // LDS.128
            const int rb = bb*17 - phase;
            #pragma unroll 1
            for (int n = n0; n < nend; ++n) {
                const int r = rb + n;
                if ((unsigned)r >= 128u) continue;
                uint64_t a1x = 0ull, a1y = 0ull, a2x = 0ull, a2y = 0ull;
                const ulonglong2* Ln = sLd + n*Nn;
                #pragma unroll
                for (int m = 0; m < Nn; ++m) {
                    ulonglong2 l = Ln[m];        // LDS.128 bcast {l1,l1 | t2,t2}
                    fma2(a1x, xq[m].x, l.x);
                    fma2(a1y, xq[m].y, l.x);
                    fma2(a2x, xq[m].x, l.y);
                    fma2(a2y, xq[m].y, l.y);
                }
                float f0, f1, f2, f3;
                uint4 o;
                unpack2(a1x, f0, f1); unpack2(a1y, f2, f3);
                o.x = cvt_tf32(f0); o.y = cvt_tf32(f1);
                o.z = cvt_tf32(f2); o.w = cvt_tf32(f3);
                *(uint4*)(sU + r*USTR + 4*q) = o;            // U1 (STS.128)
                unpack2(a2x, f0, f1); unpack2(a2y, f2, f3);
                o.x = cvt_tf32(f0); o.y = cvt_tf32(f1);
                o.z = cvt_tf32(f2); o.w = cvt_tf32(f3);
                *(uint4*)(sU + r*USTR + 128 + 4*q) = o;      // U2 (STS.128)
            }
        }
    }
    __syncthreads();

    // ---- GEMM: 3 chunks back-to-back, no further barriers (warps 0-7) ----
    if (warp < 8) {
        const int mw = warp >> 1, nw = warp & 1;    // 4x2 grid, 32x64 tiles
        const int r0 = 32 * mw;
        const int arow = r0 + g;
        float acc[2][8][4];
        #pragma unroll
        for (int mi = 0; mi < 2; ++mi)
            #pragma unroll
            for (int ni = 0; ni < 8; ++ni)
                #pragma unroll
                for (int j = 0; j < 4; ++j) acc[mi][ni][j] = 0.f;

        gemm_chunk<XSTR>(sXU + (phase + arow)*XSTR + 2*tq,
                         g_WB + (0*32 + nw)*512 + lane*16, acc);
        gemm_chunk<USTR>(sU + arow*USTR + 2*tq,
                         g_WB + (1*32 + nw)*512 + lane*16, acc);
        gemm_chunk<USTR>(sU + arow*USTR + 128 + 2*tq,
                         g_WB + (2*32 + nw)*512 + lane*16, acc);

        // ---- epilogue: bias + relu (R8 verbatim) ----
        const int d0c = 64 * nw;
        #pragma unroll
        for (int ni = 0; ni < 8; ++ni) {
            const int col = d0c + 8*ni + 2*tq;
            const float2 bv = *(const float2*)(sB + col);
            #pragma unroll
            for (int mi = 0; mi < 2; ++mi) {
                const int rr = rg0 + r0 + 16*mi + g;
                float2 v0, v1;
                v0.x = fmaxf(acc[mi][ni][0] + bv.x, 0.f);
                v0.y = fmaxf(acc[mi][ni][1] + bv.y, 0.f);
                v1.x = fmaxf(acc[mi][ni][2] + bv.x, 0.f);
                v1.y = fmaxf(acc[mi][ni][3] + bv.y, 0.f);
                *(float2*)(out + (size_t)rr*Dd + col)       = v0;
                *(float2*)(out + (size_t)(rr + 8)*Dd + col) = v1;
            }
        }
    }
}

// ---------------------------------------------------------------------------
extern "C" void kernel_launch(void* const* d_in, const int* in_sizes, int n_in,
                              void* d_out, int out_size) {
    const float* x    = (const float*)d_in[0];   // [16384,17,128]
    const float* adj  = (const float*)d_in[1];   // [17,17]
    const float* w    = (const float*)d_in[2];   // [3,1,128,128]
    const float* bias = (const float*)d_in[3];   // [1,1,128]
    float* out = (float*)d_out;                  // [16384,17,128]

    cudaFuncSetAttribute(graphcheb,
                         cudaFuncAttributeMaxDynamicSharedMemorySize, SMEM_BYTES);

    setup_kernel<<<97, 512>>>(adj, w);
    graphcheb<<<(Bn*Nn)/128, THREADS, SMEM_BYTES>>>(x, bias, out);
}

// round 16
// speedup vs baseline: 1.0257x; 1.0257x over previous
#include <cuda_runtime.h>
#include <cstdint>

// ---------------- problem constants ----------------
#define Bn 16384
#define Nn 17
#define Cc 128
#define Dd 128
#define THREADS 288            // 9 warps: 8 GEMM warps + full 9-batch coverage
#define XSTR 136               // x tile row stride (mod 32 == 8: conflict-free frags)
#define USTR 264               // U12 tile row stride (mod 32 == 8)

// ---------------- device scratch ----------------
__device__ float4 g_L12[Nn*Nn];      // {l1,l1,t2,t2} per (n,m)
__device__ float  g_WB[3*16*16*64];  // W tf32 frags; 16 contiguous floats/lane/k-step

// ---------------- smem float-index offsets (R8 layout) ----------------
#define SF_XU   0                    // 153*136 = 20808 floats
#define SF_U    20808                // 128*264 = 33792 floats (U1 | U2)
#define SF_L    54600                // 289 float4 = 1156 floats
#define SF_BIAS 55756                // 128 floats
#define SMEM_FLOATS 55884
#define SMEM_BYTES  (SMEM_FLOATS*4)  // 223536

// ---------------- helpers ----------------
__device__ __forceinline__ uint32_t cvt_tf32(float f) {
    uint32_t u; asm("cvt.rn.tf32.f32 %0, %1;" : "=r"(u) : "f"(f)); return u;
}
__device__ __forceinline__ float tf32f(float f) { return __uint_as_float(cvt_tf32(f)); }
__device__ __forceinline__ void fma2(uint64_t& acc, uint64_t a, uint64_t b) {
    asm("fma.rn.f32x2 %0, %1, %2, %0;" : "+l"(acc) : "l"(a), "l"(b));
}
__device__ __forceinline__ void unpack2(uint64_t u, float& a, float& b) {
    asm("mov.b64 {%0, %1}, %2;" : "=f"(a), "=f"(b) : "l"(u));
}
__device__ __forceinline__ uint64_t pack2f(float a, float b) {
    uint64_t u; asm("mov.b64 %0, {%1, %2};" : "=l"(u) : "f"(a), "f"(b)); return u;
}
__device__ __forceinline__ uint64_t pack2i(uint32_t a, uint32_t b) {
    uint64_t u; asm("mov.b64 %0, {%1, %2};" : "=l"(u) : "r"(a), "r"(b)); return u;
}
__device__ __forceinline__ void mma_tf32(float* d, uint32_t a0, uint32_t a1,
                                         uint32_t a2, uint32_t a3,
                                         uint32_t b0, uint32_t b1) {
    asm volatile("mma.sync.aligned.m16n8k8.row.col.f32.tf32.tf32.f32 "
        "{%0,%1,%2,%3}, {%4,%5,%6,%7}, {%8,%9}, {%0,%1,%2,%3};"
        : "+f"(d[0]), "+f"(d[1]), "+f"(d[2]), "+f"(d[3])
        : "r"(a0), "r"(a1), "r"(a2), "r"(a3), "r"(b0), "r"(b1));
}

// ---------------------------------------------------------------------------
// Merged setup. W fragment layout (LDG.128-friendly, proven R13-R15):
//   g_WB[((k*16+s)*2+nw)*512 + lane*16 + ni*2 + j]
//     = tf32( W_k[c = 8s + (lane&3) + 4j][d = (lane>>2) + 8*ni + 64*nw] )
// Block 96 computes the Chebyshev basis into g_L12.
// ---------------------------------------------------------------------------
__global__ void setup_kernel(const float* __restrict__ adj, const float* __restrict__ w) {
    __shared__ float dinv[Nn];
    __shared__ float Ls[Nn*Nn];
    if (blockIdx.x < 96) {
        int idx = blockIdx.x * 512 + threadIdx.x;     // < 49152
        int j    = idx & 1;
        int ni   = (idx >> 1) & 7;
        int lane = (idx >> 4) & 31;
        int nw   = (idx >> 9) & 1;
        int s    = (idx >> 10) & 15;
        int k    = idx >> 14;
        int c = 8*s + (lane & 3) + 4*j;
        int d = (lane >> 2) + 8*ni + 64*nw;
        g_WB[idx] = tf32f(w[k*16384 + c*128 + d]);
    } else {
        int t = threadIdx.x;
        if (t < Nn) {
            float s = 0.f;
            #pragma unroll
            for (int m = 0; m < Nn; ++m) s += adj[t*Nn + m];
            dinv[t] = rsqrtf(s);
        }
        __syncthreads();
        if (t < Nn*Nn) {
            int n = t / Nn, m = t % Nn;
            Ls[t] = (n == m ? 1.f : 0.f) - dinv[n] * adj[t] * dinv[m];
        }
        __syncthreads();
        if (t < Nn*Nn) {
            int n = t / Nn, m = t % Nn;
            float a = 0.f;
            #pragma unroll
            for (int jx = 0; jx < Nn; ++jx) a = fmaf(Ls[n*Nn + jx], Ls[jx*Nn + m], a);
            float t2 = 2.f * a - (n == m ? 1.f : 0.f);
            g_L12[t] = make_float4(Ls[t], Ls[t], t2, t2);
        }
    }
}

// ---------------------------------------------------------------------------
// GEMM chunk (R8 double-buffered structure): A frags 2x LDS.64 (pair-permuted),
// B frags 2x LDG.128 per step (new layout; was 8x LDG.64 in R8).
// ---------------------------------------------------------------------------
template<int STR>
__device__ __forceinline__ void gemm_chunk(const float* Ab, const float* Bb,
                                           float acc[2][8][4]) {
    uint2 A[2][2][2];
    uint4 B[2][4];
    #pragma unroll
    for (int mi = 0; mi < 2; ++mi) {
        A[0][mi][0] = *(const uint2*)(Ab + mi*16*STR);
        A[0][mi][1] = *(const uint2*)(Ab + mi*16*STR + 8*STR);
    }
    #pragma unroll
    for (int q = 0; q < 4; ++q) B[0][q] = *(const uint4*)(Bb + q*4);
    #pragma unroll
    for (int s = 0; s < 16; ++s) {
        const int cur = s & 1, nxt = cur ^ 1;
        if (s < 15) {
            const float* An = Ab + (s + 1) * 8;
            #pragma unroll
            for (int mi = 0; mi < 2; ++mi) {
                A[nxt][mi][0] = *(const uint2*)(An + mi*16*STR);
                A[nxt][mi][1] = *(const uint2*)(An + mi*16*STR + 8*STR);
            }
            const float* Bx = Bb + (s + 1) * 1024;
            #pragma unroll
            for (int q = 0; q < 4; ++q) B[nxt][q] = *(const uint4*)(Bx + q*4);
        }
        #pragma unroll
        for (int mi = 0; mi < 2; ++mi)
            #pragma unroll
            for (int q = 0; q < 4; ++q) {
                mma_tf32(acc[mi][2*q],   A[cur][mi][0].x, A[cur][mi][1].x,
                         A[cur][mi][0].y, A[cur][mi][1].y,
                         B[cur][q].x, B[cur][q].y);
                mma_tf32(acc[mi][2*q+1], A[cur][mi][0].x, A[cur][mi][1].x,
                         A[cur][mi][0].y, A[cur][mi][1].y,
                         B[cur][q].z, B[cur][q].w);
            }
    }
}

// ---------------------------------------------------------------------------
// Main kernel — R8 winner verbatim except the B-fragment pointers
// ---------------------------------------------------------------------------
__global__ void __launch_bounds__(THREADS, 1)
graphcheb(const float* __restrict__ x, const float* __restrict__ bias,
          float* __restrict__ out) {
    extern __shared__ float sm[];
    float* sXU = sm + SF_XU;
    float* sU  = sm + SF_U;
    const ulonglong2* sLd = (const ulonglong2*)(sm + SF_L);
    float* sB  = sm + SF_BIAS;

    const int t    = threadIdx.x;
    const int lane = t & 31;
    const int warp = t >> 5;
    const int g    = lane >> 2;
    const int tq   = lane & 3;

    const int rg0    = blockIdx.x * 128;
    const int bstart = rg0 / Nn;
    const int phase  = rg0 - bstart * Nn;
    const int nb     = (rg0 + 127) / Nn - bstart + 1;   // 8 or 9 batches staged

    // ---- prologue: x -> sXU (tf32, pair-permuted), L, bias ----
    {
        const float* xg = x + (size_t)bstart * 2176;
        const int nblk = nb * 17 * 16;
        for (int i = t; i < nblk; i += THREADS) {
            int row = i >> 4, blk = i & 15;
            const float* p = xg + row*128 + blk*8;
            float4 v0 = *(const float4*)p;
            float4 v1 = *(const float4*)(p + 4);
            uint64_t* o = (uint64_t*)(sXU + row*XSTR + blk*8);
            o[0] = pack2f(tf32f(v0.x), tf32f(v1.x));
            o[1] = pack2f(tf32f(v0.y), tf32f(v1.y));
            o[2] = pack2f(tf32f(v0.z), tf32f(v1.z));
            o[3] = pack2f(tf32f(v0.w), tf32f(v1.w));
        }
        for (int i = t; i < Nn*Nn; i += THREADS)
            ((float4*)(sm + SF_L))[i] = g_L12[i];
        if (t < Dd) sB[t] = bias[t];
    }
    __syncthreads();

    // ---- aggregation (R8 verbatim): item = (batch, col-pair) ----
    {
        const int items = nb * 64;
        for (int it = t; it < items; it += THREADS) {
            const int bb = it >> 6, p = it & 63;
            const float* xb = sXU + bb*17*XSTR + 2*p;
            uint64_t x2[Nn];
            #pragma unroll
            for (int m = 0; m < Nn; ++m) x2[m] = *(const uint64_t*)(xb + m*XSTR);
            const int rb = bb*17 - phase;
            #pragma unroll 1
            for (int n = 0; n < Nn; ++n) {
                const int r = rb + n;
                if ((unsigned)r >= 128u) continue;
                uint64_t a1 = 0ull, a2 = 0ull;
                const ulonglong2* Ln = sLd + n*Nn;
                #pragma unroll
                for (int m = 0; m < Nn; ++m) {
                    ulonglong2 l = Ln[m];          // LDS.128 broadcast {l1,l1 | t2,t2}
                    fma2(a1, x2[m], l.x);
                    fma2(a2, x2[m], l.y);
                }
                float f0, f1;
                unpack2(a1, f0, f1);
                *(uint64_t*)(sU + r*USTR + 2*p)       = pack2i(cvt_tf32(f0), cvt_tf32(f1));
                unpack2(a2, f0, f1);
                *(uint64_t*)(sU + r*USTR + 128 + 2*p) = pack2i(cvt_tf32(f0), cvt_tf32(f1));
            }
        }
    }
    __syncthreads();

    // ---- GEMM: 3 chunks back-to-back, no further barriers (warps 0-7) ----
    if (warp < 8) {
        const int mw = warp >> 1, nw = warp & 1;    // 4x2 grid, 32x64 tiles
        const int r0 = 32 * mw;
        const int arow = r0 + g;
        float acc[2][8][4];
        #pragma unroll
        for (int mi = 0; mi < 2; ++mi)
            #pragma unroll
            for (int ni = 0; ni < 8; ++ni)
                #pragma unroll
                for (int j = 0; j < 4; ++j) acc[mi][ni][j] = 0.f;

        gemm_chunk<XSTR>(sXU + (phase + arow)*XSTR + 2*tq,
                         g_WB + (0*32 + nw)*512 + lane*16, acc);
        gemm_chunk<USTR>(sU + arow*USTR + 2*tq,
                         g_WB + (1*32 + nw)*512 + lane*16, acc);
        gemm_chunk<USTR>(sU + arow*USTR + 128 + 2*tq,
                         g_WB + (2*32 + nw)*512 + lane*16, acc);

        // ---- epilogue: bias + relu (R8 verbatim) ----
        const int d0c = 64 * nw;
        #pragma unroll
        for (int ni = 0; ni < 8; ++ni) {
            const int col = d0c + 8*ni + 2*tq;
            const float2 bv = *(const float2*)(sB + col);
            #pragma unroll
            for (int mi = 0; mi < 2; ++mi) {
                const int rr = rg0 + r0 + 16*mi + g;
                float2 v0, v1;
                v0.x = fmaxf(acc[mi][ni][0] + bv.x, 0.f);
                v0.y = fmaxf(acc[mi][ni][1] + bv.y, 0.f);
                v1.x = fmaxf(acc[mi][ni][2] + bv.x, 0.f);
                v1.y = fmaxf(acc[mi][ni][3] + bv.y, 0.f);
                *(float2*)(out + (size_t)rr*Dd + col)       = v0;
                *(float2*)(out + (size_t)(rr + 8)*Dd + col) = v1;
            }
        }
    }
}

// ---------------------------------------------------------------------------
extern "C" void kernel_launch(void* const* d_in, const int* in_sizes, int n_in,
                              void* d_out, int out_size) {
    const float* x    = (const float*)d_in[0];   // [16384,17,128]
    const float* adj  = (const float*)d_in[1];   // [17,17]
    const float* w    = (const float*)d_in[2];   // [3,1,128,128]
    const float* bias = (const float*)d_in[3];   // [1,1,128]
    float* out = (float*)d_out;                  // [16384,17,128]

    cudaFuncSetAttribute(graphcheb,
                         cudaFuncAttributeMaxDynamicSharedMemorySize, SMEM_BYTES);

    setup_kernel<<<97, 512>>>(adj, w);
    graphcheb<<<(Bn*Nn)/128, THREADS, SMEM_BYTES>>>(x, bias, out);
}

// round 17
// speedup vs baseline: 1.3940x; 1.3591x over previous
#include <cuda_runtime.h>
#include <cstdint>

// ---------------- problem constants ----------------
#define Bn 16384
#define Nn 17
#define Cc 128
#define Dd 128
#define THREADS 288            // 9 warps: 8 GEMM warps + full 9-batch coverage
#define XSTR 136               // x tile row stride (mod 32 == 8: conflict-free frags)
#define USTR 264               // U12 tile row stride (mod 32 == 8)

// ---------------- device scratch ----------------
__device__ float4 g_L12[Nn*Nn];      // {l1,l1,t2,t2} per (n,m)
__device__ float  g_WB[3*16*16*64];  // W tf32 frags, coalesced-LDG.128 layout (see setup)

// ---------------- smem float-index offsets (R8 layout) ----------------
#define SF_XU   0                    // 153*136 = 20808 floats
#define SF_U    20808                // 128*264 = 33792 floats (U1 | U2)
#define SF_L    54600                // 289 float4 = 1156 floats
#define SF_BIAS 55756                // 128 floats
#define SMEM_FLOATS 55884
#define SMEM_BYTES  (SMEM_FLOATS*4)  // 223536

// ---------------- helpers ----------------
__device__ __forceinline__ uint32_t cvt_tf32(float f) {
    uint32_t u; asm("cvt.rn.tf32.f32 %0, %1;" : "=r"(u) : "f"(f)); return u;
}
__device__ __forceinline__ float tf32f(float f) { return __uint_as_float(cvt_tf32(f)); }
__device__ __forceinline__ void fma2(uint64_t& acc, uint64_t a, uint64_t b) {
    asm("fma.rn.f32x2 %0, %1, %2, %0;" : "+l"(acc) : "l"(a), "l"(b));
}
__device__ __forceinline__ void unpack2(uint64_t u, float& a, float& b) {
    asm("mov.b64 {%0, %1}, %2;" : "=f"(a), "=f"(b) : "l"(u));
}
__device__ __forceinline__ uint64_t pack2f(float a, float b) {
    uint64_t u; asm("mov.b64 %0, {%1, %2};" : "=l"(u) : "f"(a), "f"(b)); return u;
}
__device__ __forceinline__ uint64_t pack2i(uint32_t a, uint32_t b) {
    uint64_t u; asm("mov.b64 %0, {%1, %2};" : "=l"(u) : "r"(a), "r"(b)); return u;
}
__device__ __forceinline__ void mma_tf32(float* d, uint32_t a0, uint32_t a1,
                                         uint32_t a2, uint32_t a3,
                                         uint32_t b0, uint32_t b1) {
    asm volatile("mma.sync.aligned.m16n8k8.row.col.f32.tf32.tf32.f32 "
        "{%0,%1,%2,%3}, {%4,%5,%6,%7}, {%8,%9}, {%0,%1,%2,%3};"
        : "+f"(d[0]), "+f"(d[1]), "+f"(d[2]), "+f"(d[3])
        : "r"(a0), "r"(a1), "r"(a2), "r"(a3), "r"(b0), "r"(b1));
}

// ---------------------------------------------------------------------------
// Merged setup. COALESCED LDG.128 W-fragment layout:
//   idx = ((k*16+s)*2+nw)*512 + q*128 + lane*4 + e,  e = dn*2 + j, ni = 2q+dn
//   g_WB[idx] = tf32( W_k[c = 8s + (lane&3) + 4j][d = (lane>>2) + 8*ni + 64*nw] )
// A warp's uint4 load at (s,nw,q) covers 512 contiguous bytes (4 lines).
// Block 96 computes the Chebyshev basis into g_L12.
// ---------------------------------------------------------------------------
__global__ void setup_kernel(const float* __restrict__ adj, const float* __restrict__ w) {
    __shared__ float dinv[Nn];
    __shared__ float Ls[Nn*Nn];
    if (blockIdx.x < 96) {
        int idx = blockIdx.x * 512 + threadIdx.x;     // < 49152
        int e    = idx & 3;
        int lane = (idx >> 2) & 31;
        int q    = (idx >> 7) & 3;
        int nw   = (idx >> 9) & 1;
        int s    = (idx >> 10) & 15;
        int k    = idx >> 14;
        int j  = e & 1;
        int ni = 2*q + (e >> 1);
        int c = 8*s + (lane & 3) + 4*j;
        int d = (lane >> 2) + 8*ni + 64*nw;
        g_WB[idx] = tf32f(w[k*16384 + c*128 + d]);
    } else {
        int t = threadIdx.x;
        if (t < Nn) {
            float s = 0.f;
            #pragma unroll
            for (int m = 0; m < Nn; ++m) s += adj[t*Nn + m];
            dinv[t] = rsqrtf(s);
        }
        __syncthreads();
        if (t < Nn*Nn) {
            int n = t / Nn, m = t % Nn;
            Ls[t] = (n == m ? 1.f : 0.f) - dinv[n] * adj[t] * dinv[m];
        }
        __syncthreads();
        if (t < Nn*Nn) {
            int n = t / Nn, m = t % Nn;
            float a = 0.f;
            #pragma unroll
            for (int jx = 0; jx < Nn; ++jx) a = fmaf(Ls[n*Nn + jx], Ls[jx*Nn + m], a);
            float t2 = 2.f * a - (n == m ? 1.f : 0.f);
            g_L12[t] = make_float4(Ls[t], Ls[t], t2, t2);
        }
    }
}

// ---------------------------------------------------------------------------
// GEMM chunk (R8 double-buffered structure): A frags 2x LDS.64 (pair-permuted),
// B frags 4x FULLY-COALESCED LDG.128 per step (was 8x LDG.64 in R8).
// ---------------------------------------------------------------------------
template<int STR>
__device__ __forceinline__ void gemm_chunk(const float* Ab, const float* Bb,
                                           float acc[2][8][4]) {
    uint2 A[2][2][2];
    uint4 B[2][4];
    #pragma unroll
    for (int mi = 0; mi < 2; ++mi) {
        A[0][mi][0] = *(const uint2*)(Ab + mi*16*STR);
        A[0][mi][1] = *(const uint2*)(Ab + mi*16*STR + 8*STR);
    }
    #pragma unroll
    for (int q = 0; q < 4; ++q) B[0][q] = *(const uint4*)(Bb + q*128);
    #pragma unroll
    for (int s = 0; s < 16; ++s) {
        const int cur = s & 1, nxt = cur ^ 1;
        if (s < 15) {
            const float* An = Ab + (s + 1) * 8;
            #pragma unroll
            for (int mi = 0; mi < 2; ++mi) {
                A[nxt][mi][0] = *(const uint2*)(An + mi*16*STR);
                A[nxt][mi][1] = *(const uint2*)(An + mi*16*STR + 8*STR);
            }
            const float* Bx = Bb + (s + 1) * 1024;
            #pragma unroll
            for (int q = 0; q < 4; ++q) B[nxt][q] = *(const uint4*)(Bx + q*128);
        }
        #pragma unroll
        for (int mi = 0; mi < 2; ++mi)
            #pragma unroll
            for (int q = 0; q < 4; ++q) {
                mma_tf32(acc[mi][2*q],   A[cur][mi][0].x, A[cur][mi][1].x,
                         A[cur][mi][0].y, A[cur][mi][1].y,
                         B[cur][q].x, B[cur][q].y);
                mma_tf32(acc[mi][2*q+1], A[cur][mi][0].x, A[cur][mi][1].x,
                         A[cur][mi][0].y, A[cur][mi][1].y,
                         B[cur][q].z, B[cur][q].w);
            }
    }
}

// ---------------------------------------------------------------------------
// Main kernel — R8 winner verbatim except B-fragment pointers/loads
// ---------------------------------------------------------------------------
__global__ void __launch_bounds__(THREADS, 1)
graphcheb(const float* __restrict__ x, const float* __restrict__ bias,
          float* __restrict__ out) {
    extern __shared__ float sm[];
    float* sXU = sm + SF_XU;
    float* sU  = sm + SF_U;
    const ulonglong2* sLd = (const ulonglong2*)(sm + SF_L);
    float* sB  = sm + SF_BIAS;

    const int t    = threadIdx.x;
    const int lane = t & 31;
    const int warp = t >> 5;
    const int g    = lane >> 2;
    const int tq   = lane & 3;

    const int rg0    = blockIdx.x * 128;
    const int bstart = rg0 / Nn;
    const int phase  = rg0 - bstart * Nn;
    const int nb     = (rg0 + 127) / Nn - bstart + 1;   // 8 or 9 batches staged

    // ---- prologue: x -> sXU (tf32, pair-permuted), L, bias (R8 verbatim) ----
    {
        const float* xg = x + (size_t)bstart * 2176;
        const int nblk = nb * 17 * 16;
        for (int i = t; i < nblk; i += THREADS) {
            int row = i >> 4, blk = i & 15;
            const float* p = xg + row*128 + blk*8;
            float4 v0 = *(const float4*)p;
            float4 v1 = *(const float4*)(p + 4);
            uint64_t* o = (uint64_t*)(sXU + row*XSTR + blk*8);
            o[0] = pack2f(tf32f(v0.x), tf32f(v1.x));
            o[1] = pack2f(tf32f(v0.y), tf32f(v1.y));
            o[2] = pack2f(tf32f(v0.z), tf32f(v1.z));
            o[3] = pack2f(tf32f(v0.w), tf32f(v1.w));
        }
        for (int i = t; i < Nn*Nn; i += THREADS)
            ((float4*)(sm + SF_L))[i] = g_L12[i];
        if (t < Dd) sB[t] = bias[t];
    }
    __syncthreads();

    // ---- aggregation (R8 verbatim): item = (batch, col-pair) ----
    {
        const int items = nb * 64;
        for (int it = t; it < items; it += THREADS) {
            const int bb = it >> 6, p = it & 63;
            const float* xb = sXU + bb*17*XSTR + 2*p;
            uint64_t x2[Nn];
            #pragma unroll
            for (int m = 0; m < Nn; ++m) x2[m] = *(const uint64_t*)(xb + m*XSTR);
            const int rb = bb*17 - phase;
            #pragma unroll 1
            for (int n = 0; n < Nn; ++n) {
                const int r = rb + n;
                if ((unsigned)r >= 128u) continue;
                uint64_t a1 = 0ull, a2 = 0ull;
                const ulonglong2* Ln = sLd + n*Nn;
                #pragma unroll
                for (int m = 0; m < Nn; ++m) {
                    ulonglong2 l = Ln[m];          // LDS.128 broadcast {l1,l1 | t2,t2}
                    fma2(a1, x2[m], l.x);
                    fma2(a2, x2[m], l.y);
                }
                float f0, f1;
                unpack2(a1, f0, f1);
                *(uint64_t*)(sU + r*USTR + 2*p)       = pack2i(cvt_tf32(f0), cvt_tf32(f1));
                unpack2(a2, f0, f1);
                *(uint64_t*)(sU + r*USTR + 128 + 2*p) = pack2i(cvt_tf32(f0), cvt_tf32(f1));
            }
        }
    }
    __syncthreads();

    // ---- GEMM: 3 chunks back-to-back, no further barriers (warps 0-7) ----
    if (warp < 8) {
        const int mw = warp >> 1, nw = warp & 1;    // 4x2 grid, 32x64 tiles
        const int r0 = 32 * mw;
        const int arow = r0 + g;
        float acc[2][8][4];
        #pragma unroll
        for (int mi = 0; mi < 2; ++mi)
            #pragma unroll
            for (int ni = 0; ni < 8; ++ni)
                #pragma unroll
                for (int j = 0; j < 4; ++j) acc[mi][ni][j] = 0.f;

        gemm_chunk<XSTR>(sXU + (phase + arow)*XSTR + 2*tq,
                         g_WB + (0*32 + nw)*512 + lane*4, acc);
        gemm_chunk<USTR>(sU + arow*USTR + 2*tq,
                         g_WB + (1*32 + nw)*512 + lane*4, acc);
        gemm_chunk<USTR>(sU + arow*USTR + 128 + 2*tq,
                         g_WB + (2*32 + nw)*512 + lane*4, acc);

        // ---- epilogue: bias + relu (R8 verbatim) ----
        const int d0c = 64 * nw;
        #pragma unroll
        for (int ni = 0; ni < 8; ++ni) {
            const int col = d0c + 8*ni + 2*tq;
            const float2 bv = *(const float2*)(sB + col);
            #pragma unroll
            for (int mi = 0; mi < 2; ++mi) {
                const int rr = rg0 + r0 + 16*mi + g;
                float2 v0, v1;
                v0.x = fmaxf(acc[mi][ni][0] + bv.x, 0.f);
                v0.y = fmaxf(acc[mi][ni][1] + bv.y, 0.f);
                v1.x = fmaxf(acc[mi][ni][2] + bv.x, 0.f);
                v1.y = fmaxf(acc[mi][ni][3] + bv.y, 0.f);
                *(float2*)(out + (size_t)rr*Dd + col)       = v0;
                *(float2*)(out + (size_t)(rr + 8)*Dd + col) = v1;
            }
        }
    }
}

// ---------------------------------------------------------------------------
extern "C" void kernel_launch(void* const* d_in, const int* in_sizes, int n_in,
                              void* d_out, int out_size) {
    const float* x    = (const float*)d_in[0];   // [16384,17,128]
    const float* adj  = (const float*)d_in[1];   // [17,17]
    const float* w    = (const float*)d_in[2];   // [3,1,128,128]
    const float* bias = (const float*)d_in[3];   // [1,1,128]
    float* out = (float*)d_out;                  // [16384,17,128]

    cudaFuncSetAttribute(graphcheb,
                         cudaFuncAttributeMaxDynamicSharedMemorySize, SMEM_BYTES);

    setup_kernel<<<97, 512>>>(adj, w);
    graphcheb<<<(Bn*Nn)/128, THREADS, SMEM_BYTES>>>(x, bias, out);
}